// round 1
// baseline (speedup 1.0000x reference)
#include <cuda_runtime.h>

#define NWARP 4      // warps per block
#define NB 4         // batch elements per warp
#define L 64
#define C 7
#define H 32
#define NSTEPS 126   // (L-1)*K, K=2, h = 0.5

typedef unsigned long long ull;

// ---- packed dual-fp32 FMA (sm_10x) ----
__device__ __forceinline__ ull ffma2(ull a, ull b, ull c) {
    ull d;
    asm("fma.rn.f32x2 %0, %1, %2, %3;" : "=l"(d) : "l"(a), "l"(b), "l"(c));
    return d;
}
__device__ __forceinline__ ull pk2(float x, float y) {
    ull r;
    asm("mov.b64 %0, {%1, %2};" : "=l"(r) : "f"(x), "f"(y));
    return r;
}
__device__ __forceinline__ void upk2(ull v, float &x, float &y) {
    asm("mov.b64 {%0, %1}, %2;" : "=f"(x), "=f"(y) : "l"(v));
}

// stable softplus: max(x,0) + log(1+exp(-|x|)); abs err ~1e-7
__device__ __forceinline__ float sp_(float x) {
    return fmaxf(x, 0.f) + __logf(1.f + __expf(-fabsf(x)));
}
// exact-identity tanh via exp: 1 - 2/(e^{2x}+1); abs err ~1e-7
__device__ __forceinline__ float tanh_(float x) {
    float e = __expf(2.f * x);
    return 1.f - __fdividef(2.f, e + 1.f);
}

// cubic Hermite derivative: dX = m0 + (diff-m0)*f*(4-3f)
// diff = x[idx+1]-x[idx]; m0 = idx==0 ? diff : x[idx]-x[idx-1]
__device__ __forceinline__ float spline_eval(const float* __restrict__ xrow, float t) {
    int idx = (int)t;
    idx = min(idx, L - 2);
    float f = t - (float)idx;
    const float* p = xrow + idx * C;
    float x0 = __ldg(p);
    float x1 = __ldg(p + C);
    float diff = x1 - x0;
    float m0 = diff;
    if (idx > 0) m0 = x0 - __ldg(p - C);
    return fmaf((diff - m0) * f, fmaf(-3.f, f, 4.f), m0);
}

__global__ __launch_bounds__(NWARP * 32)
void cde_kernel(const float* __restrict__ X,      // (4096,64,7)
                const float* __restrict__ Winit,  // (32,7)
                const float* __restrict__ binit,  // (32)
                const float* __restrict__ Wf1,    // (32,32)
                const float* __restrict__ bf1,    // (32)
                const float* __restrict__ Wf2,    // (224,32)
                const float* __restrict__ bf2,    // (224)
                const float* __restrict__ Wo1,    // (16,32)
                const float* __restrict__ bo1,    // (16)
                const float* __restrict__ Wo2,    // (3,16)
                const float* __restrict__ bo2,    // (3)
                float* __restrict__ out)          // (4096,3)
{
    // Wf2 transposed + padded: sW2[j][h*8 + c] = Wf2[h*7+c][j], c==7 -> 0
    __shared__ __align__(16) float sW2[32][256];             // 32 KB
    __shared__ __align__(16) float sZ[NWARP][NB][32];        // 2 KB
    __shared__ __align__(16) ull   sH1[NWARP][NB][32];       // 4 KB  (duplicated pairs)
    __shared__ __align__(16) float sDX[NWARP][3][NB][8];     // 1.5 KB

    const int tid = threadIdx.x;
    const int w = tid >> 5;
    const int lane = tid & 31;

    for (int i = tid; i < 32 * 256; i += NWARP * 32) {
        int j = i >> 8, hc = i & 255, h = hc >> 3, c = hc & 7;
        sW2[j][hc] = (c < C) ? Wf2[(h * C + c) * 32 + j] : 0.f;
    }
    __syncthreads();

    const int bbase = (blockIdx.x * NWARP + w) * NB;

    // per-lane constant registers
    ull rw1[16];
    {
        const float2* p = reinterpret_cast<const float2*>(Wf1 + lane * 32);
#pragma unroll
        for (int k = 0; k < 16; k++) { float2 v = __ldg(p + k); rw1[k] = pk2(v.x, v.y); }
    }
    const float rbf1 = __ldg(bf1 + lane);
    ull rbf2[4];
#pragma unroll
    for (int cp = 0; cp < 4; cp++) {
        int c0 = 2 * cp, c1 = 2 * cp + 1;
        float a = __ldg(bf2 + lane * C + c0);
        float b = (c1 < C) ? __ldg(bf2 + lane * C + c1) : 0.f;
        rbf2[cp] = pk2(a, b);
    }

    // dX lane mapping: lane -> (batch db, channel dc)
    const int db = lane >> 3;
    const int dc = lane & 7;
    const float* xrow = X + (size_t)(bbase + db) * (L * C) + ((dc < C) ? dc : 0);

    // z0 = x[:,0] @ Winit^T + binit
    float z[NB];
#pragma unroll
    for (int b = 0; b < NB; b++) {
        float acc = __ldg(binit + lane);
        const float* xp = X + (size_t)(bbase + b) * (L * C);
#pragma unroll
        for (int c = 0; c < C; c++) acc = fmaf(__ldg(xp + c), __ldg(Winit + lane * C + c), acc);
        z[b] = acc;
    }

    // initial dX(t=0) -> slot 0  (idx=0, f=0 -> dX = x[1]-x[0])
    {
        float v = 0.f;
        if (dc < C) v = __ldg(xrow + C) - __ldg(xrow);
        sDX[w][0][db][dc] = v;
    }
    __syncwarp();

    float t0 = 0.f;
#pragma unroll 1
    for (int i = 0; i < NSTEPS; i++, t0 += 0.5f) {
        // dX at t0+0.25 -> slot 2 ; dX at t0+0.5 -> slot (i+1)&1 (becomes next step's A)
        {
            float vb = 0.f, vc = 0.f;
            if (dc < C) {
                vb = spline_eval(xrow, t0 + 0.25f);
                vc = spline_eval(xrow, t0 + 0.5f);
            }
            __syncwarp();
            sDX[w][2][db][dc] = vb;
            sDX[w][(i + 1) & 1][db][dc] = vc;
            __syncwarp();
        }
        const int slotA = i & 1;
        const int slotC = (i + 1) & 1;

        float ksum[NB], zs[NB];
#pragma unroll
        for (int b = 0; b < NB; b++) { zs[b] = z[b]; ksum[b] = 0.f; }

#pragma unroll 1
        for (int s = 0; s < 4; s++) {
            const int slot = (s == 0) ? slotA : ((s == 3) ? slotC : 2);

            // ---- vf(zs) ----
            __syncwarp();
#pragma unroll
            for (int b = 0; b < NB; b++) sZ[w][b][lane] = zs[b];
            __syncwarp();

            // mm1: h1_pre[lane] = sum_j zs[j]*Wf1[lane][j]   (packed over j)
            ull a1[NB];
#pragma unroll
            for (int b = 0; b < NB; b++) a1[b] = 0ull;
#pragma unroll
            for (int k2 = 0; k2 < 16; k2++) {
#pragma unroll
                for (int b = 0; b < NB; b++) {
                    ull zp = *reinterpret_cast<const ull*>(&sZ[w][b][2 * k2]);
                    a1[b] = ffma2(zp, rw1[k2], a1[b]);
                }
            }
            float h1[NB];
#pragma unroll
            for (int b = 0; b < NB; b++) {
                float u, v; upk2(a1[b], u, v);
                h1[b] = sp_(u + v + rbf1);
            }
            __syncwarp();
#pragma unroll
            for (int b = 0; b < NB; b++) sH1[w][b][lane] = pk2(h1[b], h1[b]);
            __syncwarp();

            // mm2: g_pre[lane*7+c] = sum_j h1[j]*Wf2[lane*7+c][j]  (packed over c)
            ull a2[NB][4];
#pragma unroll
            for (int b = 0; b < NB; b++)
#pragma unroll
                for (int cp = 0; cp < 4; cp++) a2[b][cp] = rbf2[cp];

            const float* wrow = &sW2[0][lane * 8];
#pragma unroll
            for (int j = 0; j < 32; j++) {
                ulonglong2 wa = *reinterpret_cast<const ulonglong2*>(wrow + j * 256);
                ulonglong2 wb = *reinterpret_cast<const ulonglong2*>(wrow + j * 256 + 4);
#pragma unroll
                for (int b = 0; b < NB; b++) {
                    ull hp = sH1[w][b][j];
                    a2[b][0] = ffma2(hp, wa.x, a2[b][0]);
                    a2[b][1] = ffma2(hp, wa.y, a2[b][1]);
                    a2[b][2] = ffma2(hp, wb.x, a2[b][2]);
                    a2[b][3] = ffma2(hp, wb.y, a2[b][3]);
                }
            }

            // tanh + einsum with dX
            float kk[NB];
#pragma unroll
            for (int b = 0; b < NB; b++) {
                ull e = 0ull;
#pragma unroll
                for (int cp = 0; cp < 4; cp++) {
                    float p0, p1; upk2(a2[b][cp], p0, p1);
                    ull g = pk2(tanh_(p0), tanh_(p1));
                    ull dxp = *reinterpret_cast<const ull*>(&sDX[w][slot][b][2 * cp]);
                    e = ffma2(g, dxp, e);
                }
                float e0, e1; upk2(e, e0, e1);
                kk[b] = e0 + e1;
            }

            // RK4 bookkeeping: weights 1,2,2,1 ; next-stage offsets 0.25,0.25,0.5
            const float wk = (s == 1 || s == 2) ? 2.f : 1.f;
            const float an = (s < 2) ? 0.25f : 0.5f;
#pragma unroll
            for (int b = 0; b < NB; b++) {
                ksum[b] = fmaf(wk, kk[b], ksum[b]);
                zs[b]   = fmaf(an, kk[b], z[b]);
            }
        }
#pragma unroll
        for (int b = 0; b < NB; b++) z[b] = fmaf(ksum[b], (1.f / 12.f), z[b]);  // h/6 = 1/12
    }

    // output head: out = softplus(z @ Wo1^T + bo1) @ Wo2^T + bo2
    __syncwarp();
#pragma unroll
    for (int b = 0; b < NB; b++) sZ[w][b][lane] = z[b];
    __syncwarp();
    float* so = &sDX[w][0][0][0];  // reuse as [NB][16] scratch
    if (lane < 16) {
#pragma unroll
        for (int b = 0; b < NB; b++) {
            float acc = __ldg(bo1 + lane);
#pragma unroll
            for (int hh = 0; hh < 32; hh++)
                acc = fmaf(sZ[w][b][hh], __ldg(Wo1 + lane * 32 + hh), acc);
            so[b * 16 + lane] = sp_(acc);
        }
    }
    __syncwarp();
    if (lane < 12) {
        int b = lane / 3;
        int jo = lane - 3 * b;
        float acc = __ldg(bo2 + jo);
#pragma unroll
        for (int i2 = 0; i2 < 16; i2++)
            acc = fmaf(so[b * 16 + i2], __ldg(Wo2 + jo * 16 + i2), acc);
        out[(size_t)(bbase + b) * 3 + jo] = acc;
    }
}

extern "C" void kernel_launch(void* const* d_in, const int* in_sizes, int n_in,
                              void* d_out, int out_size) {
    const float* X     = (const float*)d_in[0];
    const float* Winit = (const float*)d_in[1];
    const float* binit = (const float*)d_in[2];
    const float* Wf1   = (const float*)d_in[3];
    const float* bf1   = (const float*)d_in[4];
    const float* Wf2   = (const float*)d_in[5];
    const float* bf2   = (const float*)d_in[6];
    const float* Wo1   = (const float*)d_in[7];
    const float* bo1   = (const float*)d_in[8];
    const float* Wo2   = (const float*)d_in[9];
    const float* bo2   = (const float*)d_in[10];
    float* out = (float*)d_out;

    const int B = 4096;
    const int blocks = B / (NWARP * NB);  // 256
    cde_kernel<<<blocks, NWARP * 32>>>(X, Winit, binit, Wf1, bf1, Wf2, bf2,
                                       Wo1, bo1, Wo2, bo2, out);
}